// round 8
// baseline (speedup 1.0000x reference)
#include <cuda_runtime.h>
#include <cuda_bf16.h>

// Problem constants (match reference_code)
#define NPTS 8192
#define F0   8191      // N - 1 finite dim-0 pairs
#define E0   1
#define F1   4096
#define E1   8

// Output layout (flat fp32):
//   [0,     16382)  finite_dgm0   : rows (0, death)   -> float2 per row
//   [16382, 16383)  essential_dgm0: single 0
//   [16383, 24575)  finite_dgm1   : 2*F1 gathered dists
//   [24575, 24583)  essential_dgm1: E1 gathered dists
#define OFF_E0  (2 * F0)            // 16382
#define OFF_F1  (OFF_E0 + E0)       // 16383
#define OFF_E1  (OFF_F1 + 2 * F1)   // 24575

// Work items, exactly 16384 = 64 blocks x 256 threads (no bounds guard):
//   [0, F0)          : dgm0 row r           (2 scalar idx loads, float2 store)
//   F0               : essential_dgm0 zero  + all E1 essential dim-1 pairs
//   [F0+1, 16384)    : dim-1 flat pair j    (one int2 load)
#define ITEM_F1   (F0 + 1)   // 8192
#define N_ITEMS   16384      // = F0 + 1 + 2*F1

__device__ __forceinline__ float pair_dist(const float* __restrict__ X, int a, int b) {
    float ax = __ldg(X + 3 * a + 0);
    float ay = __ldg(X + 3 * a + 1);
    float az = __ldg(X + 3 * a + 2);
    float bx = __ldg(X + 3 * b + 0);
    float by = __ldg(X + 3 * b + 1);
    float bz = __ldg(X + 3 * b + 2);
    float dx = ax - bx, dy = ay - by, dz = az - bz;
    return sqrtf(fmaf(dx, dx, fmaf(dy, dy, dz * dz)));
}

__global__ __launch_bounds__(256, 4)
void rips_kernel(const float* __restrict__ X,
                 const int* __restrict__ idx0_finite,    // [F0,3]
                 const int* __restrict__ idx1_finite,    // [F1,4] == flat pairs [2*F1,2]
                 const int* __restrict__ idx1_essential, // [E1,2]
                 float* __restrict__ out) {
    int tid = blockIdx.x * blockDim.x + threadIdx.x;   // [0, 16384), exact

    if (tid < F0) {
        // One dgm0 row: independent index loads issue back-to-back, then six
        // X loads, then one 8B store of (0, death).
        int a = __ldg(idx0_finite + 3 * tid + 1);
        int b = __ldg(idx0_finite + 3 * tid + 2);
        float d = pair_dist(X, a, b);
        *reinterpret_cast<float2*>(out + 2 * tid) = make_float2(0.0f, d);
    } else if (tid == F0) {
        out[OFF_E0] = 0.0f;  // essential_dgm0
        // Fold the 8 essential dim-1 pairs into this otherwise-trivial thread;
        // all gathers are independent -> same two-L2-hop latency as one pair.
        #pragma unroll
        for (int k = 0; k < E1; k++) {
            int2 p = __ldg(reinterpret_cast<const int2*>(idx1_essential) + k);
            out[OFF_E1 + k] = pair_dist(X, p.x, p.y);
        }
    } else {
        int j = tid - ITEM_F1;  // flat pair index [0, 2*F1)
        int2 p = __ldg(reinterpret_cast<const int2*>(idx1_finite) + j);  // 8B-aligned
        out[OFF_F1 + j] = pair_dist(X, p.x, p.y);
    }
}

extern "C" void kernel_launch(void* const* d_in, const int* in_sizes, int n_in,
                              void* d_out, int out_size) {
    const float* X              = (const float*)d_in[0];
    const int*   idx0_finite    = (const int*)d_in[1];
    // d_in[2] = idx0_essential (unused; corresponding outputs are zeros)
    const int*   idx1_finite    = (const int*)d_in[3];
    const int*   idx1_essential = (const int*)d_in[4];
    float* out = (float*)d_out;

    rips_kernel<<<N_ITEMS / 256, 256>>>(X, idx0_finite, idx1_finite, idx1_essential, out);
}

// round 10
// speedup vs baseline: 1.3069x; 1.3069x over previous
#include <cuda_runtime.h>
#include <cuda_bf16.h>

// Problem constants (match reference_code)
#define NPTS 8192
#define F0   8191      // N - 1 finite dim-0 pairs
#define E0   1
#define F1   4096
#define E1   8

// Output layout (flat fp32):
//   [0,     16382)  finite_dgm0   : rows (0, death)   -> float2 per row
//   [16382, 16383)  essential_dgm0: single 0
//   [16383, 24575)  finite_dgm1   : 2*F1 gathered dists
//   [24575, 24583)  essential_dgm1: E1 gathered dists
#define OFF_E0  (2 * F0)            // 16382
#define OFF_F1  (OFF_E0 + E0)       // 16383
#define OFF_E1  (OFF_F1 + 2 * F1)   // 24575

// Work items (one thread each; every thread has at most 8 outstanding loads,
// well within the 16-register MLP budget — the R7 fat-thread serialization
// regression is the reason the essential pairs get their own threads):
//   [0, F0)                    : dgm0 row r            (2 scalar idx loads, float2 store)
//   F0                         : essential_dgm0 zero
//   [F0+1, F0+1+2*F1)          : dim-1 flat pair j     (one int2 load)
//   [F0+1+2*F1, +E1)           : dim-1 essential pair k (one int2 load)
#define ITEM_F1   (F0 + 1)              // 8192
#define ITEM_E1   (ITEM_F1 + 2 * F1)    // 16384
#define N_ITEMS   (ITEM_E1 + E1)        // 16392

__device__ __forceinline__ float pair_dist(const float* __restrict__ X, int a, int b) {
    float ax = __ldg(X + 3 * a + 0);
    float ay = __ldg(X + 3 * a + 1);
    float az = __ldg(X + 3 * a + 2);
    float bx = __ldg(X + 3 * b + 0);
    float by = __ldg(X + 3 * b + 1);
    float bz = __ldg(X + 3 * b + 2);
    float dx = ax - bx, dy = ay - by, dz = az - bz;
    return sqrtf(fmaf(dx, dx, fmaf(dy, dy, dz * dz)));
}

__global__ __launch_bounds__(256, 4)
void rips_kernel(const float* __restrict__ X,
                 const int* __restrict__ idx0_finite,    // [F0,3]
                 const int* __restrict__ idx1_finite,    // [F1,4] == flat pairs [2*F1,2]
                 const int* __restrict__ idx1_essential, // [E1,2]
                 float* __restrict__ out) {
    int tid = blockIdx.x * blockDim.x + threadIdx.x;
    if (tid >= N_ITEMS) return;

    if (tid < F0) {
        // One dgm0 row: independent index loads issue back-to-back, then six
        // X loads, then one 8B store of (0, death).
        int a = __ldg(idx0_finite + 3 * tid + 1);
        int b = __ldg(idx0_finite + 3 * tid + 2);
        float d = pair_dist(X, a, b);
        *reinterpret_cast<float2*>(out + 2 * tid) = make_float2(0.0f, d);
    } else if (tid == F0) {
        out[OFF_E0] = 0.0f;  // essential_dgm0
    } else if (tid < ITEM_E1) {
        int j = tid - ITEM_F1;  // flat pair index [0, 2*F1)
        int2 p = __ldg(reinterpret_cast<const int2*>(idx1_finite) + j);  // 8B-aligned
        out[OFF_F1 + j] = pair_dist(X, p.x, p.y);
    } else {
        int k = tid - ITEM_E1;
        int2 p = __ldg(reinterpret_cast<const int2*>(idx1_essential) + k);
        out[OFF_E1 + k] = pair_dist(X, p.x, p.y);
    }
}

extern "C" void kernel_launch(void* const* d_in, const int* in_sizes, int n_in,
                              void* d_out, int out_size) {
    const float* X              = (const float*)d_in[0];
    const int*   idx0_finite    = (const int*)d_in[1];
    // d_in[2] = idx0_essential (unused; corresponding outputs are zeros)
    const int*   idx1_finite    = (const int*)d_in[3];
    const int*   idx1_essential = (const int*)d_in[4];
    float* out = (float*)d_out;

    const int threads = 256;
    const int blocks = (N_ITEMS + threads - 1) / threads;  // 65
    rips_kernel<<<blocks, threads>>>(X, idx0_finite, idx1_finite, idx1_essential, out);
}

// round 11
// speedup vs baseline: 1.3469x; 1.0306x over previous
#include <cuda_runtime.h>
#include <cuda_bf16.h>

// Problem constants (match reference_code)
#define NPTS 8192
#define F0   8191      // N - 1 finite dim-0 pairs
#define E0   1
#define F1   4096
#define E1   8

// Output layout (flat fp32):
//   [0,     16382)  finite_dgm0   : rows (0, death)   -> float2 per row
//   [16382, 16383)  essential_dgm0: single 0
//   [16383, 24575)  finite_dgm1   : 2*F1 gathered dists
//   [24575, 24583)  essential_dgm1: E1 gathered dists
#define OFF_E0  (2 * F0)            // 16382
#define OFF_F1  (OFF_E0 + E0)       // 16383
#define OFF_E1  (OFF_F1 + 2 * F1)   // 24575

// Work items (one thread each; every thread has at most 8 outstanding loads,
// within the 16-register MLP budget — the R7 fat-thread serialization
// regression is why the essential pairs get their own threads):
//   [0, F0)                    : dgm0 row r            (2 scalar idx loads, float2 store)
//   F0                         : essential_dgm0 zero
//   [F0+1, F0+1+2*F1)          : dim-1 flat pair j     (one int2 load)
//   [F0+1+2*F1, +E1)           : dim-1 essential pair k (one int2 load)
#define ITEM_F1   (F0 + 1)              // 8192
#define ITEM_E1   (ITEM_F1 + 2 * F1)    // 16384
#define N_ITEMS   (ITEM_E1 + E1)        // 16392

__device__ __forceinline__ float pair_dist(const float* __restrict__ X, int a, int b) {
    float ax = __ldg(X + 3 * a + 0);
    float ay = __ldg(X + 3 * a + 1);
    float az = __ldg(X + 3 * a + 2);
    float bx = __ldg(X + 3 * b + 0);
    float by = __ldg(X + 3 * b + 1);
    float bz = __ldg(X + 3 * b + 2);
    float dx = ax - bx, dy = ay - by, dz = az - bz;
    return sqrtf(fmaf(dx, dx, fmaf(dy, dy, dz * dz)));
}

__global__ __launch_bounds__(256, 4)
void rips_kernel(const float* __restrict__ X,
                 const int* __restrict__ idx0_finite,    // [F0,3]
                 const int* __restrict__ idx1_finite,    // [F1,4] == flat pairs [2*F1,2]
                 const int* __restrict__ idx1_essential, // [E1,2]
                 float* __restrict__ out) {
    int tid = blockIdx.x * blockDim.x + threadIdx.x;
    if (tid >= N_ITEMS) return;

    if (tid < F0) {
        // One dgm0 row: independent index loads issue back-to-back, then six
        // X loads, then one 8B store of (0, death).
        int a = __ldg(idx0_finite + 3 * tid + 1);
        int b = __ldg(idx0_finite + 3 * tid + 2);
        float d = pair_dist(X, a, b);
        *reinterpret_cast<float2*>(out + 2 * tid) = make_float2(0.0f, d);
    } else if (tid == F0) {
        out[OFF_E0] = 0.0f;  // essential_dgm0
    } else if (tid < ITEM_E1) {
        int j = tid - ITEM_F1;  // flat pair index [0, 2*F1)
        int2 p = __ldg(reinterpret_cast<const int2*>(idx1_finite) + j);  // 8B-aligned
        out[OFF_F1 + j] = pair_dist(X, p.x, p.y);
    } else {
        int k = tid - ITEM_E1;
        int2 p = __ldg(reinterpret_cast<const int2*>(idx1_essential) + k);
        out[OFF_E1 + k] = pair_dist(X, p.x, p.y);
    }
}

extern "C" void kernel_launch(void* const* d_in, const int* in_sizes, int n_in,
                              void* d_out, int out_size) {
    const float* X              = (const float*)d_in[0];
    const int*   idx0_finite    = (const int*)d_in[1];
    // d_in[2] = idx0_essential (unused; corresponding outputs are zeros)
    const int*   idx1_finite    = (const int*)d_in[3];
    const int*   idx1_essential = (const int*)d_in[4];
    float* out = (float*)d_out;

    const int threads = 256;
    const int blocks = (N_ITEMS + threads - 1) / threads;  // 65
    rips_kernel<<<blocks, threads>>>(X, idx0_finite, idx1_finite, idx1_essential, out);
}